// round 14
// baseline (speedup 1.0000x reference)
#include <cuda_runtime.h>
#include <cuda_fp16.h>
#include <math.h>
#include <stdint.h>

#define NB 16
#define NN 8192
#define NC 256
#define NM 32
#define NCH 16
#define TOKCH (NN/NCH)

__device__ __half g_xq[NB*NN*NC];
__device__ unsigned int g_bkt[NB*NN];
__device__ float g_poolp[NCH*NB*NM*NC];
__device__ float g_cntp [NCH*NB*NM];
__device__ float g_k[NB*NM*NC];
__device__ float g_v[NB*NM*NC];
__device__ __half g_Aq[NB*NC*NC];
__device__ __half g_w1hh[1024*256];
__device__ __half g_w2hh[256*1024];

__device__ __forceinline__ uint32_t s2u(const void* p){
    uint32_t a; asm("{ .reg .u64 t; cvta.to.shared.u64 t, %1; cvt.u32.u64 %0, t; }" : "=r"(a) : "l"(p)); return a;
}
#define CPA(dst, src) asm volatile("cp.async.cg.shared.global [%0], [%1], 16;" :: "r"(dst), "l"(src))
#define CPCOMMIT()    asm volatile("cp.async.commit_group;" ::: "memory")
#define CPWAIT1()     asm volatile("cp.async.wait_group 1;" ::: "memory")
#define CPWAIT0()     asm volatile("cp.async.wait_group 0;" ::: "memory")
#define LDSM4(r, a) asm volatile("ldmatrix.sync.aligned.m8n8.x4.shared.b16 {%0,%1,%2,%3}, [%4];" \
    : "=r"((r)[0]), "=r"((r)[1]), "=r"((r)[2]), "=r"((r)[3]) : "r"(a))
#define MMAH(d, a, b) asm volatile( \
    "mma.sync.aligned.m16n8k16.row.col.f32.f16.f16.f32 " \
    "{%0,%1,%2,%3}, {%4,%5,%6,%7}, {%8,%9}, {%0,%1,%2,%3};" \
    : "+f"((d)[0]), "+f"((d)[1]), "+f"((d)[2]), "+f"((d)[3]) \
    : "r"((a)[0]), "r"((a)[1]), "r"((a)[2]), "r"((a)[3]), "r"((b)[0]), "r"((b)[1]))

__device__ __forceinline__ uint32_t pkh(float f0, float f1){
    __half2 h = __floats2half2_rn(f0, f1);
    return *(uint32_t*)&h;
}
__device__ __forceinline__ float geluf(float u){ return 0.5f*u*(1.f + erff(u*0.70710678118654752f)); }
__device__ __forceinline__ float wsum(float v){
    #pragma unroll
    for (int o=16;o;o>>=1) v += __shfl_xor_sync(~0u,v,o);
    return v;
}

// ---- weight transpose ----
__global__ void k_prepw(const float* __restrict__ w1, const float* __restrict__ w2){
    int n = blockIdx.x, t = threadIdx.x;
    if (n < 1024){
        float v = w1[(size_t)t*1024 + n];
        g_w1hh[n*256+t] = __float2half(v);
    } else {
        int n2 = n-1024;
        for (int k = t; k < 1024; k += 256){
            float v = w2[(size_t)k*256 + n2];
            g_w2hh[n2*1024+k] = __float2half(v);
        }
    }
}

// ---- LN1 + LSH + fp16 x ----
__global__ __launch_bounds__(256) void k_ln1(const float* __restrict__ x, const float* __restrict__ rot,
                                             const float* __restrict__ g1, const float* __restrict__ b1){
    __shared__ float rT[16*256], sg[256], sb[256];
    int tid = threadIdx.x;
    for (int i = tid; i < 4096; i += 256) rT[(i&15)*256 + (i>>4)] = rot[i];
    sg[tid] = g1[tid]; sb[tid] = b1[tid];
    __syncthreads();
    int w = tid>>5, lane = tid&31;
    int base = blockIdx.x*128 + w*16;
    for (int t0 = 0; t0 < 16; t0++){
        int row = base + t0;
        const float* xr = x + (size_t)row*NC;
        float xv[8], s = 0.f, sq = 0.f;
        #pragma unroll
        for (int j = 0; j < 8; j++){ float v = xr[lane+32*j]; xv[j] = v; s += v; sq += v*v; }
        s = wsum(s); sq = wsum(sq);
        float m = s*(1.f/256.f);
        float rs = rsqrtf(sq*(1.f/256.f) - m*m + 1e-5f);
        float r16[16];
        #pragma unroll
        for (int i = 0; i < 16; i++) r16[i] = 0.f;
        #pragma unroll
        for (int j = 0; j < 8; j++){
            int c = lane + 32*j;
            float xn = (xv[j]-m)*rs*sg[c] + sb[c];
            g_xq[(size_t)row*NC + c] = __float2half(xn);
            #pragma unroll
            for (int i = 0; i < 16; i++) r16[i] += xn * rT[i*256 + c];
        }
        #pragma unroll
        for (int i = 0; i < 16; i++){
            #pragma unroll
            for (int o = 16; o; o >>= 1) r16[i] += __shfl_xor_sync(~0u, r16[i], o);
        }
        if (!lane){
            unsigned pkb = 0;
            #pragma unroll
            for (int h = 0; h < 4; h++){
                float best = r16[h*4]; int bi = 0;
                #pragma unroll
                for (int i = 1; i < 8; i++){
                    float v = (i < 4) ? r16[h*4+i] : -r16[h*4+i-4];
                    if (v > best){ best = v; bi = i; }
                }
                pkb |= (unsigned)bi << (8*h);
            }
            g_bkt[row] = pkb;
        }
    }
}

// ---- pooling ----
__global__ __launch_bounds__(128) void k_pool(){
    extern __shared__ float sp[];
    float* scnt = sp + 4*32*256;
    int tid = threadIdx.x, w = tid>>5, lane = tid&31;
    int ch = blockIdx.x, b = blockIdx.y;
    for (int i = tid; i < 4*32*256; i += 128) sp[i] = 0.f;
    if (tid < 128) scnt[tid] = 0.f;
    __syncthreads();
    float* myp = sp + w*32*256;
    float* myc = scnt + w*32;
    int n0 = ch*TOKCH + w*(TOKCH/4);
    for (int it = 0; it < TOKCH/4; it++){
        int row = b*NN + n0 + it;
        unsigned pkb = g_bkt[row];
        const __half* xhp = g_xq + (size_t)row*NC;
        float xv[8];
        #pragma unroll
        for (int j = 0; j < 8; j++) xv[j] = __half2float(xhp[lane+32*j]);
        #pragma unroll
        for (int h = 0; h < 4; h++){
            int hm = h*8 + ((pkb >> (8*h)) & 255);
            float* dst = myp + hm*256;
            #pragma unroll
            for (int j = 0; j < 8; j++) dst[lane+32*j] += xv[j];
            if (!lane) myc[hm] += 1.f;
        }
    }
    __syncthreads();
    float* op = g_poolp + (size_t)(ch*NB + b)*NM*NC;
    for (int i = tid; i < NM*NC; i += 128)
        op[i] = sp[i] + sp[8192+i] + sp[16384+i] + sp[24576+i];
    if (tid < NM)
        g_cntp[(ch*NB+b)*NM + tid] = scnt[tid] + scnt[32+tid] + scnt[64+tid] + scnt[96+tid];
}

// ---- pooled KV projection ----
__global__ __launch_bounds__(512) void k_kv(const float* __restrict__ kvw){
    __shared__ float rp[2*256];
    __shared__ float scn[2];
    int tid = threadIdx.x;
    int mg = blockIdx.x, b = blockIdx.y;
    if (tid < 2){
        float c = 0.f;
        for (int ch = 0; ch < NCH; ch++) c += g_cntp[(ch*NB+b)*NM + mg*2 + tid];
        scn[tid] = c;
    }
    __syncthreads();
    if (tid < 512){
        int mi = tid>>8;
        float s = 0.f;
        #pragma unroll 4
        for (int ch = 0; ch < NCH; ch++)
            s += g_poolp[((size_t)(ch*NB+b)*NM + mg*2 + mi)*NC + (tid&255)];
        rp[tid] = s / (scn[mi] + 1e-20f);
    }
    __syncthreads();
    int j = tid;
    float a0 = 0.f, a1 = 0.f;
    #pragma unroll 8
    for (int c = 0; c < 256; c++){
        float wv = __ldg(kvw + (size_t)c*512 + j);
        a0 = fmaf(rp[c], wv, a0);
        a1 = fmaf(rp[256+c], wv, a1);
    }
    float* dst = (j < 256) ? g_k : g_v;
    int jj = j & 255;
    dst[((size_t)b*NM + mg*2 + 0)*NC + jj] = a0;
    dst[((size_t)b*NM + mg*2 + 1)*NC + jj] = a1;
}

// ---- A^T = scale*(q_w@k^T)^T -> fp16 ----
__global__ __launch_bounds__(256) void k_prep(const float* __restrict__ qw){
    __shared__ float ks[32*32];
    int c = threadIdx.x, b = blockIdx.x, h = blockIdx.y;
    for (int i = c; i < 1024; i += 256)
        ks[i] = g_k[((size_t)b*NM + (i>>5))*NC + h*32 + (i&31)];
    __syncthreads();
    float q[32];
    const float* qp = qw + (size_t)c*NC + h*32;
    #pragma unroll
    for (int i = 0; i < 32; i++) q[i] = qp[i];
    for (int m = 0; m < 32; m++){
        float acc = 0.f;
        #pragma unroll
        for (int i = 0; i < 32; i++) acc = fmaf(q[i], ks[m*32+i], acc);
        g_Aq[((size_t)b*256 + h*32 + m)*256 + c] = __float2half(acc*0.17677669529663689f);
    }
}

// ==== MEGA KERNEL: logits GEMM + softmax + PV + residual + LN2 + full MLP (64-row tile) ====
// smem: [0,81920) phase1 stages (2x40960) / phase3: ys[0,32K) wbb[32K,64K) hbb[64K,80K)
//       [81920,148480) Ls 64x260 f32; [148480,181248) v_s; [181248,181376) cnt;
//       [181376,181632) mu; [181632,181888) sg
__global__ __launch_bounds__(256,1) void k_attn(const float* __restrict__ x,
                                                const float* __restrict__ g2, const float* __restrict__ b2ln,
                                                const float* __restrict__ b1v, const float* __restrict__ b2v,
                                                float* __restrict__ outf){
    extern __shared__ char dsm[];
    uint32_t sb = s2u(dsm);
    float* Ls   = (float*)(dsm + 81920);
    float* v_s  = (float*)(dsm + 148480);
    float* cnt_s= (float*)(dsm + 181248);
    float* mu_s = (float*)(dsm + 181376);
    float* sg_s = (float*)(dsm + 181632);
    int tid = threadIdx.x, w = tid>>5, lane = tid&31;
    size_t row0 = (size_t)blockIdx.x*64;
    int b = blockIdx.x >> 7;
    const __half* Aq = g_Aq + (size_t)b*65536;

    for (int i = tid; i < 8192; i += 256) v_s[i] = g_v[(size_t)b*8192 + i];
    if (tid < 32){
        float c = 0.f;
        for (int ch = 0; ch < NCH; ch++) c += g_cntp[(ch*NB+b)*NM + tid];
        cnt_s[tid] = c;
    }

    // ---------------- phase 1: logits GEMM, 64x256 ----------------
    int wm = w&1, wn = w>>1;
    float acc[2][8][4];
    #pragma unroll
    for (int i = 0; i < 2; i++)
        #pragma unroll
        for (int j = 0; j < 8; j++)
            #pragma unroll
            for (int q = 0; q < 4; q++) acc[i][j][q] = 0.f;

    auto load_stage = [&](int kt, int s){
        uint32_t base = sb + s*40960;
        #pragma unroll
        for (int it = 0; it < 10; it++){
            int i = tid + it*256;
            const __half* src; uint32_t dst;
            if (i < 512){
                int r = i>>3, c = i&7;
                src = g_xq + (row0 + r)*NC + kt*64 + c*8;
                dst = base + r*128 + ((c ^ (r&7))<<4);
            } else {
                int jx = i - 512;
                int r = jx>>3, c = jx&7;
                src = Aq + (size_t)r*NC + kt*64 + c*8;
                dst = base + 8192 + r*128 + ((c ^ (r&7))<<4);
            }
            CPA(dst, src);
        }
        CPCOMMIT();
    };

    load_stage(0, 0);
    for (int kt = 0; kt < 4; kt++){
        int s = kt & 1;
        if (kt+1 < 4){ load_stage(kt+1, s^1); CPWAIT1(); }
        else CPWAIT0();
        __syncthreads();
        uint32_t As = sb + s*40960;
        uint32_t Bs = As + 8192;
        #pragma unroll
        for (int kk = 0; kk < 4; kk++){
            uint32_t ah[2][4];
            #pragma unroll
            for (int mt = 0; mt < 2; mt++){
                int r = wm*32 + mt*16 + (lane&15);
                int ch = kk*2 + ((lane>>4)&1);
                LDSM4(ah[mt], As + r*128 + ((ch ^ (r&7))<<4));
            }
            #pragma unroll
            for (int nt2 = 0; nt2 < 4; nt2++){
                uint32_t bh[4];
                int r = wn*64 + nt2*16 + (lane&7) + ((lane>>4)&1)*8;
                int ch = kk*2 + ((lane>>3)&1);
                LDSM4(bh, Bs + r*128 + ((ch ^ (r&7))<<4));
                #pragma unroll
                for (int mt = 0; mt < 2; mt++)
                    #pragma unroll
                    for (int hf = 0; hf < 2; hf++)
                        MMAH(acc[mt][nt2*2+hf], ah[mt], &bh[hf*2]);
            }
        }
        __syncthreads();
    }

    int g = lane>>2, t4 = lane&3;
    #pragma unroll
    for (int mt = 0; mt < 2; mt++){
        int R = wm*32 + mt*16 + g;
        #pragma unroll
        for (int nt = 0; nt < 8; nt++){
            int C = wn*64 + nt*8 + t4*2;
            float* d = acc[mt][nt];
            *(float2*)(Ls + R*260 + C)     = make_float2(d[0], d[1]);
            *(float2*)(Ls + (R+8)*260 + C) = make_float2(d[2], d[3]);
        }
    }
    __syncthreads();

    // ---------------- phase 2: softmax + PV + residual + LN2 -> y in smem ----------------
    float g2r[8], b2r[8];
    #pragma unroll
    for (int j = 0; j < 8; j++){ g2r[j] = g2[j*32+lane]; b2r[j] = b2ln[j*32+lane]; }
    bool valid = cnt_s[lane] >= 1.f;
    for (int t = 0; t < 8; t++){
        int rloc = w*8 + t;
        size_t row = row0 + rloc;
        float out[8];
        #pragma unroll
        for (int j = 0; j < 8; j++){
            float l = Ls[rloc*260 + j*32 + lane];
            float mxv = valid ? l : -3.0e38f;
            #pragma unroll
            for (int o = 16; o; o >>= 1) mxv = fmaxf(mxv, __shfl_xor_sync(~0u, mxv, o));
            float e = valid ? expf(l - mxv) : 0.f;
            float s = wsum(e);
            float p = e / s;
            float accv = 0.f;
            #pragma unroll
            for (int m = 0; m < 32; m++){
                float pm = __shfl_sync(~0u, p, m);
                accv = fmaf(pm, v_s[m*256 + j*32 + lane], accv);
            }
            out[j] = accv;
        }
        const float* xr = x + row*256;
        float x2v[8], s = 0.f, sq = 0.f;
        #pragma unroll
        for (int j = 0; j < 8; j++){
            float v = xr[j*32+lane] + out[j];
            x2v[j] = v; s += v; sq += v*v;
        }
        s = wsum(s); sq = wsum(sq);
        float mu = s*(1.f/256.f);
        float rs = rsqrtf(sq*(1.f/256.f) - mu*mu + 1e-5f);
        if (!lane){ mu_s[rloc] = mu; sg_s[rloc] = 1.f/rs; }
        #pragma unroll
        for (int j = 0; j < 8; j++){
            int c = j*32 + lane;
            uint32_t off = (c>>6)*8192 + rloc*128 + (((((c>>3)&7)) ^ (rloc&7))<<4) + (c&7)*2;
            *(__half*)(dsm + off) = __float2half((x2v[j]-mu)*rs*g2r[j] + b2r[j]);
        }
    }
    __syncthreads();

    // ---------------- phase 3: fused MLP from smem y ----------------
    uint32_t ysb = sb, wbb = sb + 32768, hbb = sb + 65536;

    float acc2[2][8][4];
    #pragma unroll
    for (int i = 0; i < 2; i++)
        #pragma unroll
        for (int j = 0; j < 8; j++)
            #pragma unroll
            for (int q = 0; q < 4; q++) acc2[i][j][q] = 0.f;

    auto load_w1 = [&](int nc, int kt, int s){
        uint32_t base = wbb + s*16384;
        #pragma unroll
        for (int it = 0; it < 4; it++){
            int i = tid + it*256;
            int r = i>>3, c = i&7;
            const __half* src = g_w1hh + (size_t)(nc*128 + r)*256 + kt*64 + c*8;
            uint32_t dst = base + r*128 + ((c ^ (r&7))<<4);
            CPA(dst, src);
        }
        CPCOMMIT();
    };
    auto load_w2 = [&](int nc, int cb, int s){
        int ks = cb>>1, nh = cb&1;
        uint32_t base = wbb + s*16384;
        #pragma unroll
        for (int it = 0; it < 4; it++){
            int i = tid + it*256;
            int r = i>>3, c = i&7;
            const __half* src = g_w2hh + (size_t)(nh*128 + r)*1024 + nc*128 + ks*64 + c*8;
            uint32_t dst = base + r*128 + ((c ^ (r&7))<<4);
            CPA(dst, src);
        }
        CPCOMMIT();
    };

    for (int nc = 0; nc < 8; nc++){
        float acc1[2][4][4];
        #pragma unroll
        for (int i = 0; i < 2; i++)
            #pragma unroll
            for (int j = 0; j < 4; j++)
                #pragma unroll
                for (int q = 0; q < 4; q++) acc1[i][j][q] = 0.f;

        load_w1(nc, 0, 0);
        for (int kt = 0; kt < 4; kt++){
            int s = kt & 1;
            if (kt+1 < 4){ load_w1(nc, kt+1, s^1); CPWAIT1(); }
            else CPWAIT0();
            __syncthreads();
            uint32_t As = ysb + kt*8192;
            uint32_t Bs = wbb + s*16384;
            #pragma unroll
            for (int kk = 0; kk < 4; kk++){
                uint32_t ah[2][4];
                #pragma unroll
                for (int mt = 0; mt < 2; mt++){
                    int r = wm*32 + mt*16 + (lane&15);
                    int ch = kk*2 + ((lane>>4)&1);
                    LDSM4(ah[mt], As + r*128 + ((ch ^ (r&7))<<4));
                }
                #pragma unroll
                for (int nt2 = 0; nt2 < 2; nt2++){
                    uint32_t bh[4];
                    int r = wn*32 + nt2*16 + (lane&7) + ((lane>>4)&1)*8;
                    int ch = kk*2 + ((lane>>3)&1);
                    LDSM4(bh, Bs + r*128 + ((ch ^ (r&7))<<4));
                    #pragma unroll
                    for (int mt = 0; mt < 2; mt++)
                        #pragma unroll
                        for (int hf = 0; hf < 2; hf++)
                            MMAH(acc1[mt][nt2*2+hf], ah[mt], &bh[hf*2]);
                }
            }
            __syncthreads();
        }

        #pragma unroll
        for (int mt = 0; mt < 2; mt++){
            int R = wm*32 + mt*16 + g;
            #pragma unroll
            for (int nt = 0; nt < 4; nt++){
                int cl = wn*32 + nt*8 + t4*2;
                int Cg = nc*128 + cl;
                float b0v = __ldg(b1v + Cg), b1vv = __ldg(b1v + Cg + 1);
                float* d = acc1[mt][nt];
                int ksub = cl>>6, c8 = (cl>>3)&7, cb2 = cl&7;
                uint32_t o0 = hbb + ksub*8192 + R*128     + ((c8 ^ (R&7))<<4)     + cb2*2;
                uint32_t o8 = hbb + ksub*8192 + (R+8)*128 + ((c8 ^ ((R+8)&7))<<4) + cb2*2;
                *(uint32_t*)(dsm + (o0 - sb)) = pkh(geluf(d[0]+b0v), geluf(d[1]+b1vv));
                *(uint32_t*)(dsm + (o8 - sb)) = pkh(geluf(d[2]+b0v), geluf(d[3]+b1vv));
            }
        }
        __syncthreads();

        load_w2(nc, 0, 0);
        for (int cb = 0; cb < 4; cb++){
            int s = cb & 1;
            if (cb+1 < 4){ load_w2(nc, cb+1, s^1); CPWAIT1(); }
            else CPWAIT0();
            __syncthreads();
            int ks = cb>>1, nh = cb&1;
            uint32_t As = hbb + ks*8192;
            uint32_t Bs = wbb + s*16384;
            #pragma unroll
            for (int kk = 0; kk < 4; kk++){
                uint32_t ah[2][4];
                #pragma unroll
                for (int mt = 0; mt < 2; mt++){
                    int r = wm*32 + mt*16 + (lane&15);
                    int ch = kk*2 + ((lane>>4)&1);
                    LDSM4(ah[mt], As + r*128 + ((ch ^ (r&7))<<4));
                }
                #pragma unroll
                for (int nt2 = 0; nt2 < 2; nt2++){
                    uint32_t bh[4];
                    int r = wn*32 + nt2*16 + (lane&7) + ((lane>>4)&1)*8;
                    int ch = kk*2 + ((lane>>3)&1);
                    LDSM4(bh, Bs + r*128 + ((ch ^ (r&7))<<4));
                    #pragma unroll
                    for (int mt = 0; mt < 2; mt++)
                        #pragma unroll
                        for (int hf = 0; hf < 2; hf++)
                            MMAH(acc2[mt][nh*4 + nt2*2 + hf], ah[mt], &bh[hf*2]);
                }
            }
            __syncthreads();
        }
    }

    // epilogue: out = acc2 + b2 + x2 (x2 reconstructed from y in smem)
    #pragma unroll
    for (int mt = 0; mt < 2; mt++){
        int Rl = wm*32 + mt*16 + g;
        size_t R0 = row0 + Rl;
        float mu0 = mu_s[Rl],   sg0 = sg_s[Rl];
        float mu8 = mu_s[Rl+8], sg8 = sg_s[Rl+8];
        #pragma unroll
        for (int j = 0; j < 8; j++){
            int nh = j>>2, nt2 = (j>>1)&1, hf = j&1;
            int C = nh*128 + wn*32 + nt2*16 + hf*8 + t4*2;
            float* d = acc2[mt][j];
            float b0v = __ldg(b2v + C), b1vv = __ldg(b2v + C + 1);
            float gg0 = __ldg(g2 + C), gg1 = __ldg(g2 + C + 1);
            float bt0 = __ldg(b2ln + C), bt1 = __ldg(b2ln + C + 1);
            float ig0 = 1.f/gg0, ig1 = 1.f/gg1;
            uint32_t y0off = (C>>6)*8192 + Rl*128     + (((((C>>3)&7)) ^ (Rl&7))<<4)     + (C&7)*2;
            uint32_t y8off = (C>>6)*8192 + (Rl+8)*128 + (((((C>>3)&7)) ^ ((Rl+8)&7))<<4) + (C&7)*2;
            __half2 y0 = *(__half2*)(dsm + y0off);
            __half2 y8 = *(__half2*)(dsm + y8off);
            float x2a = (__half2float(y0.x) - bt0)*ig0*sg0 + mu0;
            float x2b = (__half2float(y0.y) - bt1)*ig1*sg0 + mu0;
            float x2c = (__half2float(y8.x) - bt0)*ig0*sg8 + mu8;
            float x2d = (__half2float(y8.y) - bt1)*ig1*sg8 + mu8;
            *(float2*)(outf + R0*256 + C)     = make_float2(d[0]+b0v+x2a, d[1]+b1vv+x2b);
            *(float2*)(outf + (R0+8)*256 + C) = make_float2(d[2]+b0v+x2c, d[3]+b1vv+x2d);
        }
    }
}

extern "C" void kernel_launch(void* const* d_in, const int* in_sizes, int n_in,
                              void* d_out, int out_size) {
    const float* x   = (const float*)d_in[0];
    const float* rot = (const float*)d_in[1];
    const float* n1g = (const float*)d_in[2];
    const float* n1b = (const float*)d_in[3];
    const float* qw  = (const float*)d_in[4];
    const float* kvw = (const float*)d_in[5];
    const float* n2g = (const float*)d_in[6];
    const float* n2b = (const float*)d_in[7];
    const float* w1  = (const float*)d_in[8];
    const float* b1  = (const float*)d_in[9];
    const float* w2  = (const float*)d_in[10];
    const float* b2  = (const float*)d_in[11];
    float* out = (float*)d_out;

    const int POOL_SM = (4*32*256 + 128)*4;
    const int ASM = 181888;
    cudaFuncSetAttribute(k_pool, cudaFuncAttributeMaxDynamicSharedMemorySize, POOL_SM);
    cudaFuncSetAttribute(k_attn, cudaFuncAttributeMaxDynamicSharedMemorySize, ASM);

    k_prepw<<<1280, 256>>>(w1, w2);
    k_ln1<<<(NB*NN)/128, 256>>>(x, rot, n1g, n1b);
    k_pool<<<dim3(NCH, NB), 128, POOL_SM>>>();
    k_kv<<<dim3(16, NB), 512>>>(kvw);
    k_prep<<<dim3(NB, 8), 256>>>(qw);
    k_attn<<<(NB*NN)/64, 256, ASM>>>(x, n2g, n2b, b1, b2, out);
}

// round 15
// speedup vs baseline: 1.0390x; 1.0390x over previous
#include <cuda_runtime.h>
#include <cuda_fp16.h>
#include <math.h>
#include <stdint.h>

#define NB 16
#define NN 8192
#define NC 256
#define NM 32
#define NCH 16
#define TOKCH (NN/NCH)

__device__ __half g_xq[NB*NN*NC];
__device__ unsigned int g_bkt[NB*NN];
__device__ float g_poolp[NCH*NB*NM*NC];
__device__ float g_cntp [NCH*NB*NM];
__device__ float g_k[NB*NM*NC];
__device__ float g_v[NB*NM*NC];
__device__ __half g_Aq[NB*NC*NC];
__device__ float g_mu[NB*NN];
__device__ float g_sg[NB*NN];
__device__ __half g_y[NB*NN*NC];
__device__ __half g_w1hh[1024*256];
__device__ __half g_w2hh[256*1024];

__device__ __forceinline__ uint32_t s2u(const void* p){
    uint32_t a; asm("{ .reg .u64 t; cvta.to.shared.u64 t, %1; cvt.u32.u64 %0, t; }" : "=r"(a) : "l"(p)); return a;
}
#define CPA(dst, src) asm volatile("cp.async.cg.shared.global [%0], [%1], 16;" :: "r"(dst), "l"(src))
#define CPCOMMIT()    asm volatile("cp.async.commit_group;" ::: "memory")
#define CPWAIT1()     asm volatile("cp.async.wait_group 1;" ::: "memory")
#define CPWAIT0()     asm volatile("cp.async.wait_group 0;" ::: "memory")
#define LDSM4(r, a) asm volatile("ldmatrix.sync.aligned.m8n8.x4.shared.b16 {%0,%1,%2,%3}, [%4];" \
    : "=r"((r)[0]), "=r"((r)[1]), "=r"((r)[2]), "=r"((r)[3]) : "r"(a))
#define MMAH(d, a, b) asm volatile( \
    "mma.sync.aligned.m16n8k16.row.col.f32.f16.f16.f32 " \
    "{%0,%1,%2,%3}, {%4,%5,%6,%7}, {%8,%9}, {%0,%1,%2,%3};" \
    : "+f"((d)[0]), "+f"((d)[1]), "+f"((d)[2]), "+f"((d)[3]) \
    : "r"((a)[0]), "r"((a)[1]), "r"((a)[2]), "r"((a)[3]), "r"((b)[0]), "r"((b)[1]))

__device__ __forceinline__ uint32_t pkh(float f0, float f1){
    __half2 h = __floats2half2_rn(f0, f1);
    return *(uint32_t*)&h;
}
__device__ __forceinline__ float geluf(float u){ return 0.5f*u*(1.f + erff(u*0.70710678118654752f)); }
__device__ __forceinline__ float wsum(float v){
    #pragma unroll
    for (int o=16;o;o>>=1) v += __shfl_xor_sync(~0u,v,o);
    return v;
}

// ---- weight transpose: w1 -> fp16 [n][k], w2 -> fp16 [n][k] ----
__global__ void k_prepw(const float* __restrict__ w1, const float* __restrict__ w2){
    int n = blockIdx.x, t = threadIdx.x;
    if (n < 1024){
        float v = w1[(size_t)t*1024 + n];
        g_w1hh[n*256+t] = __float2half(v);
    } else {
        int n2 = n-1024;
        for (int k = t; k < 1024; k += 256){
            float v = w2[(size_t)k*256 + n2];
            g_w2hh[n2*1024+k] = __float2half(v);
        }
    }
}

// ---- LN1 + LSH + fp16 x ----
__global__ __launch_bounds__(256) void k_ln1(const float* __restrict__ x, const float* __restrict__ rot,
                                             const float* __restrict__ g1, const float* __restrict__ b1){
    __shared__ float rT[16*256], sg[256], sb[256];
    int tid = threadIdx.x;
    for (int i = tid; i < 4096; i += 256) rT[(i&15)*256 + (i>>4)] = rot[i];
    sg[tid] = g1[tid]; sb[tid] = b1[tid];
    __syncthreads();
    int w = tid>>5, lane = tid&31;
    int base = blockIdx.x*128 + w*16;
    for (int t0 = 0; t0 < 16; t0++){
        int row = base + t0;
        const float* xr = x + (size_t)row*NC;
        float xv[8], s = 0.f, sq = 0.f;
        #pragma unroll
        for (int j = 0; j < 8; j++){ float v = xr[lane+32*j]; xv[j] = v; s += v; sq += v*v; }
        s = wsum(s); sq = wsum(sq);
        float m = s*(1.f/256.f);
        float rs = rsqrtf(sq*(1.f/256.f) - m*m + 1e-5f);
        float r16[16];
        #pragma unroll
        for (int i = 0; i < 16; i++) r16[i] = 0.f;
        #pragma unroll
        for (int j = 0; j < 8; j++){
            int c = lane + 32*j;
            float xn = (xv[j]-m)*rs*sg[c] + sb[c];
            g_xq[(size_t)row*NC + c] = __float2half(xn);
            #pragma unroll
            for (int i = 0; i < 16; i++) r16[i] += xn * rT[i*256 + c];
        }
        #pragma unroll
        for (int i = 0; i < 16; i++){
            #pragma unroll
            for (int o = 16; o; o >>= 1) r16[i] += __shfl_xor_sync(~0u, r16[i], o);
        }
        if (!lane){
            unsigned pkb = 0;
            #pragma unroll
            for (int h = 0; h < 4; h++){
                float best = r16[h*4]; int bi = 0;
                #pragma unroll
                for (int i = 1; i < 8; i++){
                    float v = (i < 4) ? r16[h*4+i] : -r16[h*4+i-4];
                    if (v > best){ best = v; bi = i; }
                }
                pkb |= (unsigned)bi << (8*h);
            }
            g_bkt[row] = pkb;
        }
    }
}

// ---- pooling (reads fp16 x) ----
__global__ __launch_bounds__(128) void k_pool(){
    extern __shared__ float sp[];
    float* scnt = sp + 4*32*256;
    int tid = threadIdx.x, w = tid>>5, lane = tid&31;
    int ch = blockIdx.x, b = blockIdx.y;
    for (int i = tid; i < 4*32*256; i += 128) sp[i] = 0.f;
    if (tid < 128) scnt[tid] = 0.f;
    __syncthreads();
    float* myp = sp + w*32*256;
    float* myc = scnt + w*32;
    int n0 = ch*TOKCH + w*(TOKCH/4);
    for (int it = 0; it < TOKCH/4; it++){
        int row = b*NN + n0 + it;
        unsigned pkb = g_bkt[row];
        const __half* xhp = g_xq + (size_t)row*NC;
        float xv[8];
        #pragma unroll
        for (int j = 0; j < 8; j++) xv[j] = __half2float(xhp[lane+32*j]);
        #pragma unroll
        for (int h = 0; h < 4; h++){
            int hm = h*8 + ((pkb >> (8*h)) & 255);
            float* dst = myp + hm*256;
            #pragma unroll
            for (int j = 0; j < 8; j++) dst[lane+32*j] += xv[j];
            if (!lane) myc[hm] += 1.f;
        }
    }
    __syncthreads();
    float* op = g_poolp + (size_t)(ch*NB + b)*NM*NC;
    for (int i = tid; i < NM*NC; i += 128)
        op[i] = sp[i] + sp[8192+i] + sp[16384+i] + sp[24576+i];
    if (tid < NM)
        g_cntp[(ch*NB+b)*NM + tid] = scnt[tid] + scnt[32+tid] + scnt[64+tid] + scnt[96+tid];
}

// ---- pooled KV projection ----
__global__ __launch_bounds__(512) void k_kv(const float* __restrict__ kvw){
    __shared__ float rp[2*256];
    __shared__ float scn[2];
    int tid = threadIdx.x;
    int mg = blockIdx.x, b = blockIdx.y;
    if (tid < 2){
        float c = 0.f;
        for (int ch = 0; ch < NCH; ch++) c += g_cntp[(ch*NB+b)*NM + mg*2 + tid];
        scn[tid] = c;
    }
    __syncthreads();
    if (tid < 512){
        int mi = tid>>8;
        float s = 0.f;
        #pragma unroll 4
        for (int ch = 0; ch < NCH; ch++)
            s += g_poolp[((size_t)(ch*NB+b)*NM + mg*2 + mi)*NC + (tid&255)];
        rp[tid] = s / (scn[mi] + 1e-20f);
    }
    __syncthreads();
    int j = tid;
    float a0 = 0.f, a1 = 0.f;
    #pragma unroll 8
    for (int c = 0; c < 256; c++){
        float wv = __ldg(kvw + (size_t)c*512 + j);
        a0 = fmaf(rp[c], wv, a0);
        a1 = fmaf(rp[256+c], wv, a1);
    }
    float* dst = (j < 256) ? g_k : g_v;
    int jj = j & 255;
    dst[((size_t)b*NM + mg*2 + 0)*NC + jj] = a0;
    dst[((size_t)b*NM + mg*2 + 1)*NC + jj] = a1;
}

// ---- A^T = scale*(q_w@k^T)^T -> fp16 ----
__global__ __launch_bounds__(256) void k_prep(const float* __restrict__ qw){
    __shared__ float ks[32*32];
    int c = threadIdx.x, b = blockIdx.x, h = blockIdx.y;
    for (int i = c; i < 1024; i += 256)
        ks[i] = g_k[((size_t)b*NM + (i>>5))*NC + h*32 + (i&31)];
    __syncthreads();
    float q[32];
    const float* qp = qw + (size_t)c*NC + h*32;
    #pragma unroll
    for (int i = 0; i < 32; i++) q[i] = qp[i];
    for (int m = 0; m < 32; m++){
        float acc = 0.f;
        #pragma unroll
        for (int i = 0; i < 32; i++) acc = fmaf(q[i], ks[m*32+i], acc);
        g_Aq[((size_t)b*256 + h*32 + m)*256 + c] = __float2half(acc*0.17677669529663689f);
    }
}

// ---- fused: logits fp16 HMMA GEMM + softmax + PV(vT) + residual + LN2 -> fp16 y ----
// smem: [0,98304) phase1 stages (overlaps Ls, used before Ls written)
//       Ls [0,133120); vT [133120,166912) 256x33 f32; cnt [166912,167040); p_s [167040,168064)
__global__ __launch_bounds__(256,1) void k_attn(const float* __restrict__ x,
                                                const float* __restrict__ g2, const float* __restrict__ b2){
    extern __shared__ char dsm[];
    uint32_t sb = s2u(dsm);
    float* Ls   = (float*)dsm;
    float* vT   = (float*)(dsm + 133120);
    float* cnt_s= (float*)(dsm + 166912);
    float* p_s  = (float*)(dsm + 167040);
    int tid = threadIdx.x, w = tid>>5, lane = tid&31;
    size_t row0 = (size_t)blockIdx.x*128;
    int b = blockIdx.x >> 6;
    const __half* Aq = g_Aq + (size_t)b*65536;

    for (int i = tid; i < 8192; i += 256){
        int m = i>>8, c = i&255;
        vT[c*33 + m] = g_v[(size_t)b*8192 + i];
    }
    if (tid < 32){
        float c = 0.f;
        for (int ch = 0; ch < NCH; ch++) c += g_cntp[(ch*NB+b)*NM + tid];
        cnt_s[tid] = c;
    }

    int wm = w&3, wn = w>>2;
    float acc[2][16][4];
    #pragma unroll
    for (int i = 0; i < 2; i++)
        #pragma unroll
        for (int j = 0; j < 16; j++)
            #pragma unroll
            for (int q = 0; q < 4; q++) acc[i][j][q] = 0.f;

    auto load_stage = [&](int kt, int s){
        uint32_t base = sb + s*49152;
        #pragma unroll
        for (int it = 0; it < 12; it++){
            int i = tid + it*256;
            const __half* src; uint32_t dst;
            if (i < 1024){
                int r = i>>3, c = i&7;
                src = g_xq + (row0 + r)*NC + kt*64 + c*8;
                dst = base + r*128 + ((c ^ (r&7))<<4);
            } else {
                int jx = i - 1024;
                int r = jx>>3, c = jx&7;
                src = Aq + (size_t)r*NC + kt*64 + c*8;
                dst = base + 16384 + r*128 + ((c ^ (r&7))<<4);
            }
            CPA(dst, src);
        }
        CPCOMMIT();
    };

    load_stage(0, 0);
    for (int kt = 0; kt < 4; kt++){
        int s = kt & 1;
        if (kt+1 < 4){ load_stage(kt+1, s^1); CPWAIT1(); }
        else CPWAIT0();
        __syncthreads();
        uint32_t As = sb + s*49152;
        uint32_t Bs = As + 16384;
        #pragma unroll
        for (int kk = 0; kk < 4; kk++){
            uint32_t ah[2][4];
            #pragma unroll
            for (int mt = 0; mt < 2; mt++){
                int r = wm*32 + mt*16 + (lane&15);
                int ch = kk*2 + ((lane>>4)&1);
                LDSM4(ah[mt], As + r*128 + ((ch ^ (r&7))<<4));
            }
            #pragma unroll
            for (int nt2 = 0; nt2 < 8; nt2++){
                uint32_t bh[4];
                int r = wn*128 + nt2*16 + (lane&7) + ((lane>>4)&1)*8;
                int ch = kk*2 + ((lane>>3)&1);
                LDSM4(bh, Bs + r*128 + ((ch ^ (r&7))<<4));
                #pragma unroll
                for (int mt = 0; mt < 2; mt++)
                    #pragma unroll
                    for (int hf = 0; hf < 2; hf++)
                        MMAH(acc[mt][nt2*2+hf], ah[mt], &bh[hf*2]);
            }
        }
        __syncthreads();
    }

    int g = lane>>2, t4 = lane&3;
    #pragma unroll
    for (int mt = 0; mt < 2; mt++){
        int R = wm*32 + mt*16 + g;
        #pragma unroll
        for (int nt = 0; nt < 16; nt++){
            int C = wn*128 + nt*8 + t4*2;
            float* d = acc[mt][nt];
            *(float2*)(Ls + R*260 + C)     = make_float2(d[0], d[1]);
            *(float2*)(Ls + (R+8)*260 + C) = make_float2(d[2], d[3]);
        }
    }
    __syncthreads();

    float g2r[8], b2r[8];
    #pragma unroll
    for (int j = 0; j < 8; j++){ g2r[j] = g2[j*32+lane]; b2r[j] = b2[j*32+lane]; }
    bool valid = cnt_s[lane] >= 1.f;
    const float4* pv4 = (const float4*)(p_s + w*32);
    for (int t = 0; t < 16; t++){
        int rloc = w*16 + t;
        size_t row = row0 + rloc;
        float out[8];
        #pragma unroll
        for (int j = 0; j < 8; j++){
            float l = Ls[rloc*260 + j*32 + lane];
            float mxv = valid ? l : -3.0e38f;
            #pragma unroll
            for (int o = 16; o; o >>= 1) mxv = fmaxf(mxv, __shfl_xor_sync(~0u, mxv, o));
            float e = valid ? __expf(l - mxv) : 0.f;
            float s = wsum(e);
            float p = e / s;
            p_s[w*32 + lane] = p;
            __syncwarp();
            const float* vr = vT + (j*32 + lane)*33;
            float accv = 0.f;
            #pragma unroll
            for (int q = 0; q < 8; q++){
                float4 p4 = pv4[q];
                accv += p4.x*vr[4*q] + p4.y*vr[4*q+1] + p4.z*vr[4*q+2] + p4.w*vr[4*q+3];
            }
            __syncwarp();
            out[j] = accv;
        }
        const float* xr = x + row*256;
        float x2v[8], s = 0.f, sq = 0.f;
        #pragma unroll
        for (int j = 0; j < 8; j++){
            float v = xr[j*32+lane] + out[j];
            x2v[j] = v; s += v; sq += v*v;
        }
        s = wsum(s); sq = wsum(sq);
        float mu = s*(1.f/256.f);
        float rs = rsqrtf(sq*(1.f/256.f) - mu*mu + 1e-5f);
        if (!lane){ g_mu[row] = mu; g_sg[row] = 1.f/rs; }
        #pragma unroll
        for (int j = 0; j < 8; j++){
            int c = j*32 + lane;
            g_y[row*256 + c] = __float2half((x2v[j]-mu)*rs*g2r[j] + b2r[j]);
        }
    }
}

// ---- fused MLP, 64-row tile (R12 version, unchanged) ----
__global__ __launch_bounds__(256,2) void k_mlp(const float* __restrict__ b1v,
                                               const float* __restrict__ b2v,
                                               const float* __restrict__ gamma2,
                                               const float* __restrict__ beta2,
                                               float* __restrict__ outf){
    extern __shared__ char dsm[];
    uint32_t sb = s2u(dsm);
    uint32_t ysb = sb, wbb = sb + 32768, hbb = sb + 65536;
    int tid = threadIdx.x, w = tid>>5, lane = tid&31;
    size_t row0 = (size_t)blockIdx.x*64;
    int wm = w&1, wn = w>>1;

    #pragma unroll
    for (int it = 0; it < 8; it++){
        int i = tid + it*256;
        int kt = i>>9, rem = i&511;
        int r = rem>>3, c = rem&7;
        const __half* src = g_y + (row0 + r)*256 + kt*64 + c*8;
        uint32_t dst = ysb + kt*8192 + r*128 + ((c ^ (r&7))<<4);
        CPA(dst, src);
    }
    CPCOMMIT();
    CPWAIT0();
    __syncthreads();

    float acc2[2][8][4];
    #pragma unroll
    for (int i = 0; i < 2; i++)
        #pragma unroll
        for (int j = 0; j < 8; j++)
            #pragma unroll
            for (int q = 0; q < 4; q++) acc2[i][j][q] = 0.f;

    auto load_w1 = [&](int nc, int kt, int s){
        uint32_t base = wbb + s*16384;
        #pragma unroll
        for (int it = 0; it < 4; it++){
            int i = tid + it*256;
            int r = i>>3, c = i&7;
            const __half* src = g_w1hh + (size_t)(nc*128 + r)*256 + kt*64 + c*8;
            uint32_t dst = base + r*128 + ((c ^ (r&7))<<4);
            CPA(dst, src);
        }
        CPCOMMIT();
    };
    auto load_w2 = [&](int nc, int cb, int s){
        int ks = cb>>1, nh = cb&1;
        uint32_t base = wbb + s*16384;
        #pragma unroll
        for (int it = 0; it < 4; it++){
            int i = tid + it*256;
            int r = i>>3, c = i&7;
            const __half* src = g_w2hh + (size_t)(nh*128 + r)*1024 + nc*128 + ks*64 + c*8;
            uint32_t dst = base + r*128 + ((c ^ (r&7))<<4);
            CPA(dst, src);
        }
        CPCOMMIT();
    };

    int g = lane>>2, t4 = lane&3;

    for (int nc = 0; nc < 8; nc++){
        float acc1[2][4][4];
        #pragma unroll
        for (int i = 0; i < 2; i++)
            #pragma unroll
            for (int j = 0; j < 4; j++)
                #pragma unroll
                for (int q = 0; q < 4; q++) acc1[i][j][q] = 0.f;

        load_w1(nc, 0, 0);
        for (int kt = 0; kt < 4; kt++){
            int s = kt & 1;
            if (kt+1 < 4){ load_w1(nc, kt+1, s^1); CPWAIT1(); }
            else CPWAIT0();
            __syncthreads();
            uint32_t As = ysb + kt*8192;
            uint32_t Bs = wbb + s*16384;
            #pragma unroll
            for (int kk = 0; kk < 4; kk++){
                uint32_t ah[2][4];
                #pragma unroll
                for (int mt = 0; mt < 2; mt++){
                    int r = wm*32 + mt*16 + (lane&15);
                    int ch = kk*2 + ((lane>>4)&1);
                    LDSM4(ah[mt], As + r*128 + ((ch ^ (r&7))<<4));
                }
                #pragma unroll
                for (int nt2 = 0; nt2 < 2; nt2++){
                    uint32_t bh[4];
                    int r = wn*32 + nt2*16 + (lane&7) + ((lane>>4)&1)*8;
                    int ch = kk*2 + ((lane>>3)&1);
                    LDSM4(bh, Bs + r*128 + ((ch ^ (r&7))<<4));
                    #pragma unroll
                    for (int mt = 0; mt < 2; mt++)
                        #pragma unroll
                        for (int hf = 0; hf < 2; hf++)
                            MMAH(acc1[mt][nt2*2+hf], ah[mt], &bh[hf*2]);
                }
            }
            __syncthreads();
        }

        #pragma unroll
        for (int mt = 0; mt < 2; mt++){
            int R = wm*32 + mt*16 + g;
            #pragma unroll
            for (int nt = 0; nt < 4; nt++){
                int cl = wn*32 + nt*8 + t4*2;
                int Cg = nc*128 + cl;
                float b0v = __ldg(b1v + Cg), b1vv = __ldg(b1v + Cg + 1);
                float* d = acc1[mt][nt];
                int ksub = cl>>6, c8 = (cl>>3)&7, cb2 = cl&7;
                uint32_t o0 = hbb + ksub*8192 + R*128     + ((c8 ^ (R&7))<<4)     + cb2*2;
                uint32_t o8 = hbb + ksub*8192 + (R+8)*128 + ((c8 ^ ((R+8)&7))<<4) + cb2*2;
                *(uint32_t*)(dsm + (o0 - sb)) = pkh(geluf(d[0]+b0v), geluf(d[1]+b1vv));
                *(uint32_t*)(dsm + (o8 - sb)) = pkh(geluf(d[2]+b0v), geluf(d[3]+b1vv));
            }
        }
        __syncthreads();

        load_w2(nc, 0, 0);
        for (int cb = 0; cb < 4; cb++){
            int s = cb & 1;
            if (cb+1 < 4){ load_w2(nc, cb+1, s^1); CPWAIT1(); }
            else CPWAIT0();
            __syncthreads();
            int ks = cb>>1, nh = cb&1;
            uint32_t As = hbb + ks*8192;
            uint32_t Bs = wbb + s*16384;
            #pragma unroll
            for (int kk = 0; kk < 4; kk++){
                uint32_t ah[2][4];
                #pragma unroll
                for (int mt = 0; mt < 2; mt++){
                    int r = wm*32 + mt*16 + (lane&15);
                    int ch = kk*2 + ((lane>>4)&1);
                    LDSM4(ah[mt], As + r*128 + ((ch ^ (r&7))<<4));
                }
                #pragma unroll
                for (int nt2 = 0; nt2 < 2; nt2++){
                    uint32_t bh[4];
                    int r = wn*32 + nt2*16 + (lane&7) + ((lane>>4)&1)*8;
                    int ch = kk*2 + ((lane>>3)&1);
                    LDSM4(bh, Bs + r*128 + ((ch ^ (r&7))<<4));
                    #pragma unroll
                    for (int mt = 0; mt < 2; mt++)
                        #pragma unroll
                        for (int hf = 0; hf < 2; hf++)
                            MMAH(acc2[mt][nh*4 + nt2*2 + hf], ah[mt], &bh[hf*2]);
                }
            }
            __syncthreads();
        }
    }

    #pragma unroll
    for (int mt = 0; mt < 2; mt++){
        int Rl = wm*32 + mt*16 + g;
        size_t R0 = row0 + Rl;
        float mu0 = g_mu[R0],   sg0 = g_sg[R0];
        float mu8 = g_mu[R0+8], sg8 = g_sg[R0+8];
        #pragma unroll
        for (int j = 0; j < 8; j++){
            int nh = j>>2, nt2 = (j>>1)&1, hf = j&1;
            int C = nh*128 + wn*32 + nt2*16 + hf*8 + t4*2;
            float* d = acc2[mt][j];
            float b0v = __ldg(b2v + C), b1vv = __ldg(b2v + C + 1);
            float gg0 = __ldg(gamma2 + C), gg1 = __ldg(gamma2 + C + 1);
            float bt0 = __ldg(beta2 + C),  bt1 = __ldg(beta2 + C + 1);
            float ig0 = 1.f/gg0, ig1 = 1.f/gg1;
            uint32_t y0off = (C>>6)*8192 + Rl*128     + (((((C>>3)&7)) ^ (Rl&7))<<4)     + (C&7)*2;
            uint32_t y8off = (C>>6)*8192 + (Rl+8)*128 + (((((C>>3)&7)) ^ ((Rl+8)&7))<<4) + (C&7)*2;
            __half2 y0 = *(__half2*)(dsm + y0off);
            __half2 y8 = *(__half2*)(dsm + y8off);
            float x2a = (__half2float(y0.x) - bt0)*ig0*sg0 + mu0;
            float x2b = (__half2float(y0.y) - bt1)*ig1*sg0 + mu0;
            float x2c = (__half2float(y8.x) - bt0)*ig0*sg8 + mu8;
            float x2d = (__half2float(y8.y) - bt1)*ig1*sg8 + mu8;
            *(float2*)(outf + R0*256 + C)     = make_float2(d[0]+b0v+x2a, d[1]+b1vv+x2b);
            *(float2*)(outf + (R0+8)*256 + C) = make_float2(d[2]+b0v+x2c, d[3]+b1vv+x2d);
        }
    }
}

extern "C" void kernel_launch(void* const* d_in, const int* in_sizes, int n_in,
                              void* d_out, int out_size) {
    const float* x   = (const float*)d_in[0];
    const float* rot = (const float*)d_in[1];
    const float* n1g = (const float*)d_in[2];
    const float* n1b = (const float*)d_in[3];
    const float* qw  = (const float*)d_in[4];
    const float* kvw = (const float*)d_in[5];
    const float* n2g = (const float*)d_in[6];
    const float* n2b = (const float*)d_in[7];
    const float* w1  = (const float*)d_in[8];
    const float* b1  = (const float*)d_in[9];
    const float* w2  = (const float*)d_in[10];
    const float* b2  = (const float*)d_in[11];
    float* out = (float*)d_out;

    const int POOL_SM = (4*32*256 + 128)*4;
    const int ASM = 168064;
    const int MSM = 81920;
    cudaFuncSetAttribute(k_pool, cudaFuncAttributeMaxDynamicSharedMemorySize, POOL_SM);
    cudaFuncSetAttribute(k_attn, cudaFuncAttributeMaxDynamicSharedMemorySize, ASM);
    cudaFuncSetAttribute(k_mlp,  cudaFuncAttributeMaxDynamicSharedMemorySize, MSM);

    k_prepw<<<1280, 256>>>(w1, w2);
    k_ln1<<<(NB*NN)/128, 256>>>(x, rot, n1g, n1b);
    k_pool<<<dim3(NCH, NB), 128, POOL_SM>>>();
    k_kv<<<dim3(16, NB), 512>>>(kvw);
    k_prep<<<dim3(NB, 8), 256>>>(qw);
    k_attn<<<(NB*NN)/128, 256, ASM>>>(x, n2g, n2b);
    k_mlp<<<(NB*NN)/64, 256, MSM>>>(b1, b2, n2g, n2b, out);
}